// round 17
// baseline (speedup 1.0000x reference)
#include <cuda_runtime.h>
#include <cuda_bf16.h>
#include <cstdint>

// Capsule routing, factorized. Fused tf32-MMA routing kernel (REDG into g_S)
// + thin decomposed caps kernels (A: S@W partials, B: squash+V, SQf: out).
// u (32,1024,256) f32; W (256,2048) f32; out (32,32,64) f32.

#define BB 32
#define II 1024
#define CC 256
#define NN 32
#define DD 64
#define ND 2048
#define ICH 16

typedef unsigned int uint;

__device__ float g_part[BB * 8 * CC];            // colsum partials
__device__ float g_V[NN * BB * CC];              // V[n][b][c]  (relaid!)
__device__ float g_S[BB * NN * CC];              // S via REDG (zeroed by A)
__device__ float g_Opart[4 * BB * NN * DD];      // phase-A partials [cq][b][n][d]

__device__ __forceinline__ uint tf32c(float f) {
    uint r; asm("cvt.rna.tf32.f32 %0, %1;" : "=r"(r) : "f"(f)); return r;
}
__device__ __forceinline__ void mma_tf32(float* d, uint a0, uint a1, uint a2, uint a3,
                                         uint b0, uint b1) {
    asm("mma.sync.aligned.m16n8k8.row.col.f32.tf32.tf32.f32 "
        "{%0,%1,%2,%3},{%4,%5,%6,%7},{%8,%9},{%0,%1,%2,%3};"
        : "+f"(d[0]), "+f"(d[1]), "+f"(d[2]), "+f"(d[3])
        : "r"(a0), "r"(a1), "r"(a2), "r"(a3), "r"(b0), "r"(b1));
}
__device__ __forceinline__ uint4 cvt4(float4 v) {
    return make_uint4(tf32c(v.x), tf32c(v.y), tf32c(v.z), tf32c(v.w));
}

// ---- colsum partials ----------------------------------------------------
__global__ void k_colsum_part(const float* __restrict__ u) {
    int q = blockIdx.x, b = blockIdx.y, c = threadIdx.x;
    const float* p = u + (size_t)b * II * CC + (size_t)q * 128 * CC + c;
    float s = 0.f;
#pragma unroll 8
    for (int i = 0; i < 128; i++) s += p[(size_t)i * CC];
    g_part[(b * 8 + q) * CC + c] = s;
}

// ---- fused routing pass (REDG into g_S) ---------------------------------
#define FSM ((96 * 260 + 64 * 36) * 4)
__global__ __launch_bounds__(256) void k_fused(const float* __restrict__ u) {
    extern __shared__ uint smraw[];
    uint (*sU)[260] = (uint(*)[260])smraw;
    uint (*sV)[260] = (uint(*)[260])(smraw + 64 * 260);
    float (*sCf)[36] = (float(*)[36])(smraw + 96 * 260);

    int ich = blockIdx.x, b = blockIdx.y;
    int i0 = ich * 64;
    int t = threadIdx.x, lane = t & 31, w = t >> 5;
    int g4 = lane >> 2, j4 = lane & 3;

#pragma unroll
    for (int it = 0; it < 8; it++) {
        int idx = it * 256 + t, row = idx >> 6, c4 = idx & 63;
        // g_V layout [n][b][c]
        float4 v = *(const float4*)(g_V + ((size_t)row * BB + b) * CC + c4 * 4);
        *(uint4*)&sV[row][c4 * 4] = cvt4(v);
    }
#pragma unroll
    for (int it = 0; it < 16; it++) {
        int idx = it * 256 + t, row = idx >> 6, c4 = idx & 63;
        float4 v = *(const float4*)(u + ((size_t)b * II + i0 + row) * CC + c4 * 4);
        *(uint4*)&sU[row][c4 * 4] = cvt4(v);
    }
    __syncthreads();

    {   // phase 1: logits[64i x 32n] = U @ V^T
        int mt1 = w >> 1, nb = (w & 1) * 2;
        float acc1[2][4] = {};
#pragma unroll 8
        for (int ks = 0; ks < 32; ks++) {
            int k0 = ks * 8;
            uint a0 = sU[mt1 * 16 + g4][k0 + j4];
            uint a1 = sU[mt1 * 16 + g4 + 8][k0 + j4];
            uint a2 = sU[mt1 * 16 + g4][k0 + j4 + 4];
            uint a3 = sU[mt1 * 16 + g4 + 8][k0 + j4 + 4];
#pragma unroll
            for (int ntl = 0; ntl < 2; ntl++) {
                int nt = nb + ntl;
                uint b0 = sV[nt * 8 + g4][k0 + j4];
                uint b1 = sV[nt * 8 + g4][k0 + j4 + 4];
                mma_tf32(acc1[ntl], a0, a1, a2, a3, b0, b1);
            }
        }
#pragma unroll
        for (int ntl = 0; ntl < 2; ntl++) {
            int nt = nb + ntl, ncol = nt * 8 + 2 * j4;
            *(float2*)&sCf[mt1 * 16 + g4][ncol] =
                make_float2(acc1[ntl][0], acc1[ntl][1]);
            *(float2*)&sCf[mt1 * 16 + g4 + 8][ncol] =
                make_float2(acc1[ntl][2], acc1[ntl][3]);
        }
    }
    __syncthreads();

    if (t < 64) {   // softmax over n
        float vv[NN];
        float m = -1e30f;
#pragma unroll
        for (int n = 0; n < NN; n++) { vv[n] = sCf[t][n]; m = fmaxf(m, vv[n]); }
        float s = 0.f;
#pragma unroll
        for (int n = 0; n < NN; n++) { vv[n] = __expf(vv[n] - m); s += vv[n]; }
        float inv = 1.0f / s;
#pragma unroll
        for (int n = 0; n < NN; n++) sCf[t][n] = vv[n] * inv;
    }
    __syncthreads();

    {   // phase 2: S += coef^T @ U_chunk (REDG)
        float acc2[2][4][4] = {};
#pragma unroll
        for (int ks = 0; ks < 8; ks++) {
            int k0 = ks * 8;
            uint a[2][4];
#pragma unroll
            for (int mt = 0; mt < 2; mt++) {
                a[mt][0] = tf32c(sCf[k0 + j4][mt * 16 + g4]);
                a[mt][1] = tf32c(sCf[k0 + j4][mt * 16 + g4 + 8]);
                a[mt][2] = tf32c(sCf[k0 + j4 + 4][mt * 16 + g4]);
                a[mt][3] = tf32c(sCf[k0 + j4 + 4][mt * 16 + g4 + 8]);
            }
#pragma unroll
            for (int ct = 0; ct < 4; ct++) {
                int c = w * 32 + ct * 8 + g4;
                uint b0 = sU[k0 + j4][c];
                uint b1 = sU[k0 + j4 + 4][c];
#pragma unroll
                for (int mt = 0; mt < 2; mt++)
                    mma_tf32(acc2[mt][ct], a[mt][0], a[mt][1], a[mt][2], a[mt][3],
                             b0, b1);
            }
        }
        float* sp = g_S + (size_t)b * NN * CC;
#pragma unroll
        for (int mt = 0; mt < 2; mt++)
#pragma unroll
            for (int ct = 0; ct < 4; ct++) {
                int cpos = w * 32 + ct * 8 + 2 * j4;
                int n0 = mt * 16 + g4;
                atomicAdd(sp + (size_t)n0 * CC + cpos,       acc2[mt][ct][0]);
                atomicAdd(sp + (size_t)n0 * CC + cpos + 1,   acc2[mt][ct][1]);
                atomicAdd(sp + (size_t)(n0 + 8) * CC + cpos,     acc2[mt][ct][2]);
                atomicAdd(sp + (size_t)(n0 + 8) * CC + cpos + 1, acc2[mt][ct][3]);
            }
    }
}

// ---- capsA: g_Opart[cq][b][n][d] = S[b][n][cq-slice] @ W[cq-slice][n*64+d]
// grid (n=32, cq=4), 256 thr. mode0: S from colsum/32; mode1: g_S (+zero).
__global__ __launch_bounds__(256) void k_capsA(const float* __restrict__ W, int mode) {
    __shared__ float sW[64][68];
    __shared__ float sS[32][68];
    int n = blockIdx.x, cq = blockIdx.y;
    int t = threadIdx.x, lane = t & 31, w = t >> 5;

#pragma unroll
    for (int it = 0; it < 4; it++) {
        int idx = it * 256 + t, cl = idx >> 4, d4 = (idx & 15) * 4;
        *(float4*)&sW[cl][d4] =
            *(const float4*)(W + (size_t)(cq * 64 + cl) * ND + n * DD + d4);
    }
#pragma unroll
    for (int it = 0; it < 8; it++) {
        int idx = it * 256 + t, b = idx >> 6, cl = idx & 63;
        float s;
        if (mode == 0) {
            s = 0.f;
#pragma unroll 4
            for (int q = 0; q < 8; q++)
                s += g_part[(b * 8 + q) * CC + cq * 64 + cl];
            s *= (1.0f / 32.0f);
        } else {
            size_t off = ((size_t)b * NN + n) * CC + cq * 64 + cl;
            s = g_S[off];
            g_S[off] = 0.f;
        }
        sS[b][cl] = s;
    }
    __syncthreads();

    float acc[4][2] = {};
#pragma unroll
    for (int kq = 0; kq < 16; kq++) {
        float4 s4[4];
#pragma unroll
        for (int j = 0; j < 4; j++) s4[j] = *(float4*)&sS[w * 4 + j][kq * 4];
#pragma unroll
        for (int kk = 0; kk < 4; kk++) {
            float w0 = sW[kq * 4 + kk][lane];
            float w1 = sW[kq * 4 + kk][lane + 32];
#pragma unroll
            for (int j = 0; j < 4; j++) {
                float sv = (kk == 0) ? s4[j].x : (kk == 1) ? s4[j].y
                         : (kk == 2) ? s4[j].z : s4[j].w;
                acc[j][0] += sv * w0;
                acc[j][1] += sv * w1;
            }
        }
    }
#pragma unroll
    for (int j = 0; j < 4; j++) {
        size_t base = (((size_t)cq * BB + w * 4 + j) * NN + n) * DD;
        g_Opart[base + lane] = acc[j][0];
        g_Opart[base + lane + 32] = acc[j][1];
    }
}

// ---- capsB: inline squash + V[n][b][c] = O[b][:] @ W[c][:]^T ------------
// grid (n=32, ch=2), 256 thr. lane=b, warp w -> 16 c; O row in registers.
__global__ __launch_bounds__(256) void k_capsB(const float* __restrict__ W) {
    __shared__ float sO[32][65];
    __shared__ float sNrm[32];
    int n = blockIdx.x, ch = blockIdx.y;
    int t = threadIdx.x, lane = t & 31, w = t >> 5;

    // stage O = sum of 4 cq partials
#pragma unroll
    for (int it = 0; it < 8; it++) {
        int idx = it * 256 + t, b = idx >> 6, dl = idx & 63;
        float x = 0.f;
#pragma unroll
        for (int cq = 0; cq < 4; cq++)
            x += g_Opart[(((size_t)cq * BB + b) * NN + n) * DD + dl];
        sO[b][dl] = x;
    }
    __syncthreads();
    // norms: thread (b = t>>3, octet t&7)
    {
        int b = t >> 3, oct = t & 7;
        float p = 0.f;
#pragma unroll
        for (int m = 0; m < 8; m++) { float x = sO[b][oct * 8 + m]; p += x * x; }
        p += __shfl_xor_sync(0xffffffffu, p, 4);
        p += __shfl_xor_sync(0xffffffffu, p, 2);
        p += __shfl_xor_sync(0xffffffffu, p, 1);
        if (oct == 0) sNrm[b] = rsqrtf(p + 1e-7f);
    }
    __syncthreads();

    // O row (b = lane) scaled into registers
    float oreg[DD];
    {
        float f = sNrm[lane];
#pragma unroll
        for (int dl = 0; dl < DD; dl++) oreg[dl] = sO[lane][dl] * f;
    }

    // V: 16 c per warp, 4 at a time; W loads lane-uniform float4
#pragma unroll
    for (int cc = 0; cc < 16; cc += 4) {
        int cbase = ch * 128 + w * 16 + cc;
        float4 a0 = {}, a1 = {}, a2 = {}, a3 = {};
#pragma unroll
        for (int dq = 0; dq < 16; dq++) {
            const float* wb = W + (size_t)cbase * ND + n * DD + dq * 4;
            float4 w0 = *(const float4*)(wb);
            float4 w1 = *(const float4*)(wb + ND);
            float4 w2 = *(const float4*)(wb + 2 * ND);
            float4 w3 = *(const float4*)(wb + 3 * ND);
            float o0 = oreg[dq * 4], o1 = oreg[dq * 4 + 1];
            float o2 = oreg[dq * 4 + 2], o3 = oreg[dq * 4 + 3];
            a0.x += w0.x * o0; a0.y += w0.y * o1; a0.z += w0.z * o2; a0.w += w0.w * o3;
            a1.x += w1.x * o0; a1.y += w1.y * o1; a1.z += w1.z * o2; a1.w += w1.w * o3;
            a2.x += w2.x * o0; a2.y += w2.y * o1; a2.z += w2.z * o2; a2.w += w2.w * o3;
            a3.x += w3.x * o0; a3.y += w3.y * o1; a3.z += w3.z * o2; a3.w += w3.w * o3;
        }
        float4 res = make_float4(a0.x + a0.y + a0.z + a0.w,
                                 a1.x + a1.y + a1.z + a1.w,
                                 a2.x + a2.y + a2.z + a2.w,
                                 a3.x + a3.y + a3.z + a3.w);
        *(float4*)(g_V + ((size_t)n * BB + lane) * CC + cbase) = res;
    }
}

// ---- final squash -> dout -----------------------------------------------
// grid (b=32, ng=4), 256 thr; warp w -> n = ng*8+w; lane -> d, d+32.
__global__ __launch_bounds__(256) void k_sqout(float* __restrict__ dout) {
    int b = blockIdx.x, ng = blockIdx.y;
    int t = threadIdx.x, lane = t & 31, w = t >> 5;
    int n = ng * 8 + w;
    float x0 = 0.f, x1 = 0.f;
#pragma unroll
    for (int cq = 0; cq < 4; cq++) {
        size_t base = (((size_t)cq * BB + b) * NN + n) * DD;
        x0 += g_Opart[base + lane];
        x1 += g_Opart[base + lane + 32];
    }
    float sq = x0 * x0 + x1 * x1;
#pragma unroll
    for (int off = 16; off; off >>= 1) sq += __shfl_xor_sync(0xffffffffu, sq, off);
    float f = rsqrtf(sq + 1e-7f);
    dout[((size_t)b * NN + n) * DD + lane] = x0 * f;
    dout[((size_t)b * NN + n) * DD + lane + 32] = x1 * f;
}

// ---------------------------------------------------------------------------
extern "C" void kernel_launch(void* const* d_in, const int* in_sizes, int n_in,
                              void* d_out, int out_size) {
    const float* u = (const float*)d_in[0];
    const float* W = (const float*)d_in[1];
    if (n_in >= 2 && in_sizes[0] == CC * ND) {
        u = (const float*)d_in[1];
        W = (const float*)d_in[0];
    }
    float* out = (float*)d_out;

    cudaFuncSetAttribute(k_fused, cudaFuncAttributeMaxDynamicSharedMemorySize, FSM);

    k_colsum_part<<<dim3(8, BB), 256>>>(u);
    k_capsA<<<dim3(NN, 4), 256>>>(W, 0);     // S0 @ W -> g_Opart
    k_capsB<<<dim3(NN, 2), 256>>>(W);        // squash -> V0

    k_fused<<<dim3(ICH, BB), 256, FSM>>>(u); // REDG into g_S
    k_capsA<<<dim3(NN, 4), 256>>>(W, 1);     // S1 @ W (+zero g_S)
    k_capsB<<<dim3(NN, 2), 256>>>(W);        // squash -> V1

    k_fused<<<dim3(ICH, BB), 256, FSM>>>(u);
    k_capsA<<<dim3(NN, 4), 256>>>(W, 1);     // S2 @ W (+zero g_S)
    k_sqout<<<dim3(BB, 4), 256>>>(out);      // final squash -> out
}